// round 2
// baseline (speedup 1.0000x reference)
#include <cuda_runtime.h>
#include <math.h>

#define BATCH 32
#define INC 3
#define OUTC 64
#define IMG 64
#define PH 32
#define NL 16
#define LEAFW 128
#define OUTW 100

typedef unsigned long long u64;

__device__ __forceinline__ u64 pack2(float lo, float hi) {
    u64 r; asm("mov.b64 %0, {%1, %2};" : "=l"(r) : "f"(lo), "f"(hi)); return r;
}
__device__ __forceinline__ float lo2(u64 v) { return __uint_as_float((unsigned)v); }
__device__ __forceinline__ float hi2(u64 v) { return __uint_as_float((unsigned)(v >> 32)); }
__device__ __forceinline__ void fma2(u64& d, u64 a, u64 b) {
    asm("fma.rn.f32x2 %0, %1, %2, %0;" : "+l"(d) : "l"(a), "l"(b));
}
__device__ __forceinline__ u64 mul2(u64 a, u64 b) {
    u64 d; asm("mul.rn.f32x2 %0, %1, %2;" : "=l"(d) : "l"(a), "l"(b)); return d;
}
__device__ __forceinline__ u64 add2(u64 a, u64 b) {
    u64 d; asm("add.rn.f32x2 %0, %1, %2;" : "=l"(d) : "l"(a), "l"(b)); return d;
}

// Load a 6-value window row (cols cb..cb+5, cb even, 8B-aligned) as 5 packed pairs.
__device__ __forceinline__ void loadrow(u64 P[5], const float* p) {
    u64 q0 = *(const u64*)(p);      // {v0,v1}
    u64 q2 = *(const u64*)(p + 2);  // {v2,v3}
    u64 q4 = *(const u64*)(p + 4);  // {v4,v5}
    P[0] = q0; P[2] = q2; P[4] = q4;
    P[1] = pack2(hi2(q0), lo2(q2)); // {v1,v2}
    P[3] = pack2(hi2(q2), lo2(q4)); // {v3,v4}
}

// Scratch
__device__ float g_h1[NL * BATCH * OUTC * PH * PH];
__device__ float g_feat[NL * BATCH * OUTC];
__device__ float g_scores[BATCH * 4];
__device__ float g_mix[BATCH * NL];
__device__ float g_logits[NL * BATCH * OUTW];

// ---------------------------------------------------------------------------
// Routing
// ---------------------------------------------------------------------------
__global__ void k_route(const float* __restrict__ x, const float* __restrict__ nw) {
    int b = blockIdx.x, d = blockIdx.y, t = threadIdx.x;
    __shared__ float sw_[INC * 25];
    __shared__ float red[256];
    const float* w = nw + ((2 << d) - 2) * INC * 25;
    for (int i = t; i < INC * 25; i += 256) sw_[i] = w[i];
    __syncthreads();
    const float* xb = x + (long)b * INC * IMG * IMG;
    float m = -1e30f;
    for (int p = t; p < IMG * IMG; p += 256) {
        int y = p >> 6, xx = p & 63;
        float s = 0.f;
        #pragma unroll
        for (int c = 0; c < INC; c++)
            #pragma unroll
            for (int ky = 0; ky < 5; ky++) {
                int iy = y + ky - 2;
                if (iy < 0 || iy >= IMG) continue;
                #pragma unroll
                for (int kx = 0; kx < 5; kx++) {
                    int ix = xx + kx - 2;
                    if (ix < 0 || ix >= IMG) continue;
                    s += __ldg(&xb[(c << 12) + (iy << 6) + ix]) * sw_[c * 25 + ky * 5 + kx];
                }
            }
        m = fmaxf(m, s);
    }
    red[t] = m;
    __syncthreads();
    for (int s = 128; s > 0; s >>= 1) {
        if (t < s) red[t] = fmaxf(red[t], red[t + s]);
        __syncthreads();
    }
    if (t == 0) g_scores[b * 4 + d] = red[0];
}

__global__ void k_mix(const float* __restrict__ nb) {
    int t = threadIdx.x;
    if (t >= BATCH * NL) return;
    int b = t >> 4, l = t & 15;
    float m = 1.f;
    #pragma unroll
    for (int d = 0; d < 4; d++) {
        int j = l >> (4 - d);
        int bit = (l >> (3 - d)) & 1;
        float z = g_scores[b * 4 + d] + nb[(1 << d) - 1 + j];
        float be = 1.f / (1.f + expf(-z));
        m *= bit ? be : (1.f - be);
    }
    g_mix[b * NL + l] = m;
}

// ---------------------------------------------------------------------------
// conv1 (3->64) + maxpool2 + relu, FFMA2 column-pair scheme.
// grid: (l*32+b, og 0..7, yt 0..3); block 256 = 8 warps (one oc each).
// lane cp=0..31 -> pre-pool column pair (2cp,2cp+1) = pooled column cp.
// Each thread: 16 pre-pool rows (acc pairs), pool+relu in epilogue.
// ---------------------------------------------------------------------------
__global__ void __launch_bounds__(256) k_conv1(const float* __restrict__ x,
                                               const float* __restrict__ cw1) {
    __shared__ float sx[INC][20][68];   // 16.3 KB
    __shared__ u64 sw1[8][INC][25];     // 4.8 KB duplicated weight pairs

    int lb = blockIdx.x;
    int l = lb >> 5, b = lb & 31;
    int og = blockIdx.y;
    int yt = blockIdx.z;
    int t = threadIdx.x;
    int warp = t >> 5, cp = t & 31;
    int oc = og * 8 + warp;

    // slab: global rows 16*yt-2 .. 16*yt+17, cols -2..65
    for (int idx = t; idx < INC * 20 * 68; idx += 256) {
        int c = idx / (20 * 68);
        int rem = idx % (20 * 68);
        int yy = rem / 68, xx = rem % 68;
        int gy = yt * 16 + yy - 2, gx = xx - 2;
        float v = 0.f;
        if (gy >= 0 && gy < IMG && gx >= 0 && gx < IMG)
            v = x[(((long)b * INC + c) * IMG + gy) * IMG + gx];
        sx[c][yy][xx] = v;
    }
    for (int idx = t; idx < 8 * INC * 25; idx += 256) {
        int w8 = idx / (INC * 25);
        int rem = idx % (INC * 25);
        float wv = cw1[(((long)l * OUTC + og * 8 + w8) * INC) * 25 + rem];
        ((u64*)sw1)[idx] = pack2(wv, wv);
    }
    __syncthreads();

    u64 acc[16];
    u64 Z = pack2(0.f, 0.f);
    #pragma unroll
    for (int i = 0; i < 16; i++) acc[i] = Z;

    int cb = 2 * cp;

    #pragma unroll
    for (int ic = 0; ic < INC; ic++) {
        u64 w[25];
        #pragma unroll
        for (int k = 0; k < 25; k++) w[k] = sw1[warp][ic][k];

        u64 P[5][5];
        #pragma unroll
        for (int r = 0; r < 4; r++) loadrow(P[r], &sx[ic][r][cb]);

        #pragma unroll
        for (int y = 0; y < 16; y++) {
            loadrow(P[(y + 4) % 5], &sx[ic][y + 4][cb]);
            u64 a = acc[y];
            u64 bb = mul2(P[(y + 1) % 5][0], w[5]);
            #pragma unroll
            for (int ky = 0; ky < 5; ky++) {
                int rs = (y + ky) % 5;
                #pragma unroll
                for (int kx = 0; kx < 5; kx++) {
                    if (ky == 1 && kx == 0) continue;
                    if (ky & 1) fma2(bb, P[rs][kx], w[ky * 5 + kx]);
                    else        fma2(a,  P[rs][kx], w[ky * 5 + kx]);
                }
            }
            acc[y] = add2(a, bb);
        }
    }

    // pool 2x2 + relu, write pooled rows yt*8 .. yt*8+7, col cp
    #pragma unroll
    for (int pr = 0; pr < 8; pr++) {
        u64 A = acc[2 * pr], B = acc[2 * pr + 1];
        float m = fmaxf(fmaxf(lo2(A), hi2(A)), fmaxf(lo2(B), hi2(B)));
        m = fmaxf(m, 0.f);
        g_h1[((((long)l * BATCH + b) * OUTC + oc) * PH + yt * 8 + pr) * PH + cp] = m;
    }
}

// ---------------------------------------------------------------------------
// conv2 (64->64 on 32x32) + relu + global max, FFMA2 column-pair scheme.
// grid: (l*32+b, og 0..7); block 256 = 8 warps (one oc each).
// lane: cp = lane&15 (column pair 2cp,2cp+1), h = lane>>4 (row half).
// Dynamic smem: input chunk [8][36][36] + duplicated weight pairs [8][8][25].
// ---------------------------------------------------------------------------
#define ICC 8
__global__ void __launch_bounds__(256) k_conv2(const float* __restrict__ cw2) {
    extern __shared__ float dsm[];
    float* sinp = dsm;                      // ICC*36*36 = 10368 floats
    u64* sw2 = (u64*)(dsm + ICC * 36 * 36); // 8*ICC*25 pairs

    int lb = blockIdx.x;
    int l = lb >> 5, b = lb & 31;
    int og = blockIdx.y;
    int t = threadIdx.x;
    int warp = t >> 5, lane = t & 31;
    int cp = lane & 15, h = lane >> 4;
    int oc = og * 8 + warp;
    int r0 = h * 16;
    int cb = 2 * cp;

    u64 acc[16];
    u64 Z = pack2(0.f, 0.f);
    #pragma unroll
    for (int i = 0; i < 16; i++) acc[i] = Z;

    const float* h1base = &g_h1[(((long)l * BATCH + b) * OUTC) * PH * PH];

    #pragma unroll 1
    for (int cc = 0; cc < 8; cc++) {
        __syncthreads();
        // load input chunk with zero halo
        for (int idx = t; idx < ICC * 36 * 36; idx += 256) {
            int c = idx / 1296;
            int rem = idx % 1296;
            int yy = rem / 36, xx = rem % 36;
            int gy = yy - 2, gx = xx - 2;
            float v = 0.f;
            if (gy >= 0 && gy < PH && gx >= 0 && gx < PH)
                v = h1base[((cc * ICC + c) * PH + gy) * PH + gx];
            sinp[idx] = v;
        }
        // load duplicated weight pairs
        for (int idx = t; idx < 8 * ICC * 25; idx += 256) {
            int w8 = idx / (ICC * 25);
            int rem = idx % (ICC * 25);
            int ic = rem / 25, kk = rem % 25;
            float wv = cw2[(((long)l * OUTC + og * 8 + w8) * OUTC + cc * ICC + ic) * 25 + kk];
            sw2[idx] = pack2(wv, wv);
        }
        __syncthreads();

        #pragma unroll 1
        for (int ic = 0; ic < ICC; ic++) {
            u64 w[25];
            #pragma unroll
            for (int k = 0; k < 25; k++) w[k] = sw2[(warp * ICC + ic) * 25 + k];

            const float* base = sinp + ic * 1296;
            u64 P[5][5];
            #pragma unroll
            for (int r = 0; r < 4; r++) loadrow(P[r], base + (r0 + r) * 36 + cb);

            #pragma unroll
            for (int y = 0; y < 16; y++) {
                loadrow(P[(y + 4) % 5], base + (r0 + y + 4) * 36 + cb);
                u64 a = acc[y];
                u64 bb = mul2(P[(y + 1) % 5][0], w[5]);
                #pragma unroll
                for (int ky = 0; ky < 5; ky++) {
                    int rs = (y + ky) % 5;
                    #pragma unroll
                    for (int kx = 0; kx < 5; kx++) {
                        if (ky == 1 && kx == 0) continue;
                        if (ky & 1) fma2(bb, P[rs][kx], w[ky * 5 + kx]);
                        else        fma2(a,  P[rs][kx], w[ky * 5 + kx]);
                    }
                }
                acc[y] = add2(a, bb);
            }
        }
    }

    // relu + max over this thread's 32 outputs, then warp-reduce
    float m = -1e30f;
    #pragma unroll
    for (int i = 0; i < 16; i++) m = fmaxf(m, fmaxf(lo2(acc[i]), hi2(acc[i])));
    m = fmaxf(m, 0.f);
    #pragma unroll
    for (int off = 16; off > 0; off >>= 1)
        m = fmaxf(m, __shfl_xor_sync(0xffffffffu, m, off));
    if (lane == 0) g_feat[((long)l * BATCH + b) * OUTC + oc] = m;
}

// ---------------------------------------------------------------------------
// Per-leaf MLP
// ---------------------------------------------------------------------------
__global__ void k_mlp(const float* __restrict__ w1, const float* __restrict__ b1,
                      const float* __restrict__ w2, const float* __restrict__ b2) {
    int lb = blockIdx.x;
    int l = lb >> 5, b = lb & 31;
    int t = threadIdx.x;
    __shared__ float sfeat[OUTC];
    __shared__ float shid[LEAFW];
    if (t < OUTC) sfeat[t] = g_feat[((long)l * BATCH + b) * OUTC + t];
    __syncthreads();
    float hsum = b1[l * LEAFW + t];
    #pragma unroll 8
    for (int k = 0; k < OUTC; k++)
        hsum = fmaf(sfeat[k], w1[((long)l * OUTC + k) * LEAFW + t], hsum);
    shid[t] = hsum;
    __syncthreads();
    if (t < OUTW) {
        float o = b2[l * OUTW + t];
        #pragma unroll 8
        for (int j = 0; j < LEAFW; j++)
            o = fmaf(shid[j], w2[((long)l * LEAFW + j) * OUTW + t], o);
        g_logits[((long)l * BATCH + b) * OUTW + t] = o;
    }
}

__global__ void k_final(float* __restrict__ out) {
    int b = blockIdx.x;
    int t = threadIdx.x;
    if (t < OUTW) {
        float s = 0.f;
        #pragma unroll
        for (int l = 0; l < NL; l++)
            s = fmaf(g_logits[((long)l * BATCH + b) * OUTW + t], g_mix[b * NL + l], s);
        out[b * OUTW + t] = s;
    }
}

// ---------------------------------------------------------------------------
extern "C" void kernel_launch(void* const* d_in, const int* in_sizes, int n_in,
                              void* d_out, int out_size) {
    const float* x   = (const float*)d_in[0];
    const float* nw  = (const float*)d_in[1];
    const float* nb  = (const float*)d_in[2];
    const float* cw1 = (const float*)d_in[3];
    const float* cw2 = (const float*)d_in[4];
    const float* w1  = (const float*)d_in[5];
    const float* b1  = (const float*)d_in[6];
    const float* w2  = (const float*)d_in[7];
    const float* b2  = (const float*)d_in[8];
    float* out = (float*)d_out;

    static int smem_set = 0;
    int smem_bytes = ICC * 36 * 36 * 4 + 8 * ICC * 25 * 8;  // 41472 + 12800 = 54272
    if (!smem_set) {
        cudaFuncSetAttribute(k_conv2, cudaFuncAttributeMaxDynamicSharedMemorySize, smem_bytes);
        smem_set = 1;
    }

    k_route<<<dim3(BATCH, 4), 256>>>(x, nw);
    k_mix<<<1, 512>>>(nb);
    k_conv1<<<dim3(NL * BATCH, 8, 4), 256>>>(x, cw1);
    k_conv2<<<dim3(NL * BATCH, 8), 256, smem_bytes>>>(cw2);
    k_mlp<<<NL * BATCH, 128>>>(w1, b1, w2, b2);
    k_final<<<BATCH, 128>>>(out);
}

// round 3
// speedup vs baseline: 2.4992x; 2.4992x over previous
#include <cuda_runtime.h>
#include <math.h>

#define BATCH 32
#define INC 3
#define OUTC 64
#define IMG 64
#define PH 32
#define NL 16
#define LEAFW 128
#define OUTW 100

typedef unsigned long long u64;

// Scratch
__device__ float g_h1[NL * BATCH * OUTC * PH * PH];
__device__ float g_feat[NL * BATCH * OUTC];
__device__ float g_scores[BATCH * 4];
__device__ float g_mix[BATCH * NL];
__device__ float g_logits[NL * BATCH * OUTW];

__device__ __forceinline__ float to_tf32(float x) {
    float r; asm("cvt.rna.tf32.f32 %0, %1;" : "=f"(r) : "f"(x)); return r;
}
__device__ __forceinline__ void mma_tf32(float* c, unsigned a0, unsigned a1,
                                         unsigned a2, unsigned a3,
                                         unsigned b0, unsigned b1) {
    asm("mma.sync.aligned.m16n8k8.row.col.f32.tf32.tf32.f32 "
        "{%0,%1,%2,%3}, {%4,%5,%6,%7}, {%8,%9}, {%0,%1,%2,%3};"
        : "+f"(c[0]), "+f"(c[1]), "+f"(c[2]), "+f"(c[3])
        : "r"(a0), "r"(a1), "r"(a2), "r"(a3), "r"(b0), "r"(b1));
}

// ---------------------------------------------------------------------------
// Routing
// ---------------------------------------------------------------------------
__global__ void k_route(const float* __restrict__ x, const float* __restrict__ nw) {
    int b = blockIdx.x, d = blockIdx.y, t = threadIdx.x;
    __shared__ float sw_[INC * 25];
    __shared__ float red[256];
    const float* w = nw + ((2 << d) - 2) * INC * 25;
    for (int i = t; i < INC * 25; i += 256) sw_[i] = w[i];
    __syncthreads();
    const float* xb = x + (long)b * INC * IMG * IMG;
    float m = -1e30f;
    for (int p = t; p < IMG * IMG; p += 256) {
        int y = p >> 6, xx = p & 63;
        float s = 0.f;
        #pragma unroll
        for (int c = 0; c < INC; c++)
            #pragma unroll
            for (int ky = 0; ky < 5; ky++) {
                int iy = y + ky - 2;
                if (iy < 0 || iy >= IMG) continue;
                #pragma unroll
                for (int kx = 0; kx < 5; kx++) {
                    int ix = xx + kx - 2;
                    if (ix < 0 || ix >= IMG) continue;
                    s += __ldg(&xb[(c << 12) + (iy << 6) + ix]) * sw_[c * 25 + ky * 5 + kx];
                }
            }
        m = fmaxf(m, s);
    }
    red[t] = m;
    __syncthreads();
    for (int s = 128; s > 0; s >>= 1) {
        if (t < s) red[t] = fmaxf(red[t], red[t + s]);
        __syncthreads();
    }
    if (t == 0) g_scores[b * 4 + d] = red[0];
}

// Mixture weights; also zeroes g_feat (conv2 accumulates into it via atomicMax)
__global__ void k_mix(const float* __restrict__ nb) {
    int t = threadIdx.x;
    for (int i = t; i < NL * BATCH * OUTC; i += 512) g_feat[i] = 0.f;
    if (t >= BATCH * NL) return;
    int b = t >> 4, l = t & 15;
    float m = 1.f;
    #pragma unroll
    for (int d = 0; d < 4; d++) {
        int j = l >> (4 - d);
        int bit = (l >> (3 - d)) & 1;
        float z = g_scores[b * 4 + d] + nb[(1 << d) - 1 + j];
        float be = 1.f / (1.f + expf(-z));
        m *= bit ? be : (1.f - be);
    }
    g_mix[b * NL + l] = m;
}

// ---------------------------------------------------------------------------
// conv1 (3->64, 5x5, SAME) + maxpool2 + relu  -> g_h1  (R0 scalar version)
// ---------------------------------------------------------------------------
__global__ void __launch_bounds__(256) k_conv1(const float* __restrict__ x,
                                               const float* __restrict__ cw1) {
    __shared__ float sx[INC][36][68];
    __shared__ float sw_[16 * INC * 25];

    int lb = blockIdx.x;
    int l = lb >> 5, b = lb & 31;
    int og = blockIdx.y;
    int yt = blockIdx.z;
    int t = threadIdx.x;

    for (int idx = t; idx < INC * 36 * 68; idx += 256) {
        int c = idx / (36 * 68);
        int rem = idx % (36 * 68);
        int yy = rem / 68, xx = rem % 68;
        int gy = yt * 32 + yy - 2, gx = xx - 2;
        float v = 0.f;
        if (gy >= 0 && gy < IMG && gx >= 0 && gx < IMG)
            v = x[(((long)b * INC + c) * IMG + gy) * IMG + gx];
        sx[c][yy][xx] = v;
    }
    for (int idx = t; idx < 16 * INC * 25; idx += 256) {
        sw_[idx] = cw1[(((long)l * OUTC + og * 16) * INC) * 25 + idx];
    }
    __syncthreads();

    int oc_l = t >> 4;
    int lane16 = t & 15;
    int oc = og * 16 + oc_l;

    #pragma unroll 1
    for (int ps = 0; ps < 2; ps++) {
        int pc = lane16 + ps * 16;
        #pragma unroll 1
        for (int py = 0; py < 16; py++) {
            float a00 = 0.f, a01 = 0.f, a10 = 0.f, a11 = 0.f;
            #pragma unroll
            for (int c = 0; c < INC; c++) {
                float win[6][6];
                #pragma unroll
                for (int r = 0; r < 6; r++)
                    #pragma unroll
                    for (int q = 0; q < 6; q++)
                        win[r][q] = sx[c][2 * py + r][2 * pc + q];
                const float* wp = &sw_[(oc_l * INC + c) * 25];
                #pragma unroll
                for (int ky = 0; ky < 5; ky++)
                    #pragma unroll
                    for (int kx = 0; kx < 5; kx++) {
                        float wv = wp[ky * 5 + kx];
                        a00 = fmaf(win[ky][kx], wv, a00);
                        a01 = fmaf(win[ky][kx + 1], wv, a01);
                        a10 = fmaf(win[ky + 1][kx], wv, a10);
                        a11 = fmaf(win[ky + 1][kx + 1], wv, a11);
                    }
            }
            float v = fmaxf(fmaxf(a00, a01), fmaxf(a10, a11));
            v = fmaxf(v, 0.f);
            int prow = yt * 16 + py;
            g_h1[((((long)l * BATCH + b) * OUTC + oc) * PH + prow) * PH + pc] = v;
        }
    }
}

// ---------------------------------------------------------------------------
// conv2 via tensor cores (tf32 mma.sync m16n8k8), implicit GEMM.
// grid: (l*32+b, q=0..3). block 256 = 8 warps.
// Each block: all 64 oc x 256 spatial (rows q*8..q*8+7, 32 cols).
// warp: wm = wid&3 -> oc base wm*16; wn = wid>>2 -> local rows wn*4..wn*4+3.
// K loop: 8 chunks of 8 input channels x 25 taps.
// smem: s_w[tap][oc][icperm] (tf32), s_in[12][36][icperm] (tf32, halo).
// icperm p = 2*(ic&3) + (ic>>2)  => mma k-rows {c, c+4} are adjacent (LDS.64).
// Epilogue: relu + max -> atomicMax into g_feat (zeroed by k_mix).
// ---------------------------------------------------------------------------
__global__ void __launch_bounds__(256) k_conv2(const float* __restrict__ cw2) {
    extern __shared__ float dsm[];
    float* s_w = dsm;                 // 25*64*8 = 12800 floats
    float* s_in = dsm + 12800;        // 12*36*8 = 3456 floats

    int lb = blockIdx.x;
    int l = lb >> 5, b = lb & 31;
    int q = blockIdx.y;
    int t = threadIdx.x;
    int wid = t >> 5, lane = t & 31;
    int wm = wid & 3, wn = wid >> 2;
    int g = lane >> 2, c4 = lane & 3;

    float acc[16][4];
    #pragma unroll
    for (int j = 0; j < 16; j++)
        #pragma unroll
        for (int k = 0; k < 4; k++) acc[j][k] = 0.f;

    const float* h1base = g_h1 + (long)(l * BATCH + b) * OUTC * PH * PH;
    const float* wbase = cw2 + (long)l * OUTC * OUTC * 25;

    #pragma unroll 1
    for (int cc = 0; cc < 8; cc++) {
        __syncthreads();
        // weights: consecutive threads read consecutive taps (coalesced)
        for (int idx = t; idx < 12800; idx += 256) {
            int tap = idx % 25;
            int oi = idx / 25;          // (oc, ic)
            int ic = oi & 7, oc = oi >> 3;
            float v = wbase[(oc * OUTC + cc * 8 + ic) * 25 + tap];
            int p = ((ic & 3) << 1) | (ic >> 2);
            s_w[(tap << 9) + (oc << 3) + p] = to_tf32(v);
        }
        // input slab 12x36 with halo, ic-permuted innermost
        for (int idx = t; idx < 3456; idx += 256) {
            int xx = idx % 36;
            int yy = (idx / 36) % 12;
            int ic = idx / 432;
            int gy = q * 8 + yy - 2, gx = xx - 2;
            float v = 0.f;
            if (gy >= 0 && gy < PH && gx >= 0 && gx < PH)
                v = h1base[(cc * 8 + ic) * PH * PH + gy * PH + gx];
            int p = ((ic & 3) << 1) | (ic >> 2);
            s_in[((yy * 36 + xx) << 3) + p] = to_tf32(v);
        }
        __syncthreads();

        const float* pA = s_w + ((wm * 16 + g) << 3) + 2 * c4;
        const float* pB0 = s_in + (((wn * 4) * 36 + g) << 3) + 2 * c4;

        #pragma unroll 1
        for (int ky = 0; ky < 5; ky++) {
            #pragma unroll 1
            for (int kx = 0; kx < 5; kx++) {
                int tap = ky * 5 + kx;
                u64 a02 = *(const u64*)(pA + (tap << 9));
                u64 a13 = *(const u64*)(pA + (tap << 9) + 64);
                unsigned a0 = (unsigned)a02, a2 = (unsigned)(a02 >> 32);
                unsigned a1 = (unsigned)a13, a3 = (unsigned)(a13 >> 32);
                const float* pB = pB0 + ((ky * 36 + kx) << 3);
                #pragma unroll
                for (int j = 0; j < 16; j++) {
                    u64 bb = *(const u64*)(pB + (((j >> 2) * 36 + (j & 3) * 8) << 3));
                    mma_tf32(acc[j], a0, a1, a2, a3,
                             (unsigned)bb, (unsigned)(bb >> 32));
                }
            }
        }
    }

    // relu + max; c0/c1 -> oc = wm*16+g ; c2/c3 -> oc = wm*16+g+8
    float mlo = -1e30f, mhi = -1e30f;
    #pragma unroll
    for (int j = 0; j < 16; j++) {
        mlo = fmaxf(mlo, fmaxf(acc[j][0], acc[j][1]));
        mhi = fmaxf(mhi, fmaxf(acc[j][2], acc[j][3]));
    }
    mlo = fmaxf(mlo, 0.f);
    mhi = fmaxf(mhi, 0.f);
    #pragma unroll
    for (int off = 1; off <= 2; off <<= 1) {
        mlo = fmaxf(mlo, __shfl_xor_sync(0xffffffffu, mlo, off));
        mhi = fmaxf(mhi, __shfl_xor_sync(0xffffffffu, mhi, off));
    }
    if (c4 == 0) {
        int base = (l * BATCH + b) * OUTC + wm * 16 + g;
        atomicMax((int*)&g_feat[base], __float_as_int(mlo));
        atomicMax((int*)&g_feat[base + 8], __float_as_int(mhi));
    }
}

// ---------------------------------------------------------------------------
// Per-leaf MLP
// ---------------------------------------------------------------------------
__global__ void k_mlp(const float* __restrict__ w1, const float* __restrict__ b1,
                      const float* __restrict__ w2, const float* __restrict__ b2) {
    int lb = blockIdx.x;
    int l = lb >> 5, b = lb & 31;
    int t = threadIdx.x;
    __shared__ float sfeat[OUTC];
    __shared__ float shid[LEAFW];
    if (t < OUTC) sfeat[t] = g_feat[((long)l * BATCH + b) * OUTC + t];
    __syncthreads();
    float hsum = b1[l * LEAFW + t];
    #pragma unroll 8
    for (int k = 0; k < OUTC; k++)
        hsum = fmaf(sfeat[k], w1[((long)l * OUTC + k) * LEAFW + t], hsum);
    shid[t] = hsum;
    __syncthreads();
    if (t < OUTW) {
        float o = b2[l * OUTW + t];
        #pragma unroll 8
        for (int j = 0; j < LEAFW; j++)
            o = fmaf(shid[j], w2[((long)l * LEAFW + j) * OUTW + t], o);
        g_logits[((long)l * BATCH + b) * OUTW + t] = o;
    }
}

__global__ void k_final(float* __restrict__ out) {
    int b = blockIdx.x;
    int t = threadIdx.x;
    if (t < OUTW) {
        float s = 0.f;
        #pragma unroll
        for (int l = 0; l < NL; l++)
            s = fmaf(g_logits[((long)l * BATCH + b) * OUTW + t], g_mix[b * NL + l], s);
        out[b * OUTW + t] = s;
    }
}

// ---------------------------------------------------------------------------
extern "C" void kernel_launch(void* const* d_in, const int* in_sizes, int n_in,
                              void* d_out, int out_size) {
    const float* x   = (const float*)d_in[0];
    const float* nw  = (const float*)d_in[1];
    const float* nb  = (const float*)d_in[2];
    const float* cw1 = (const float*)d_in[3];
    const float* cw2 = (const float*)d_in[4];
    const float* w1  = (const float*)d_in[5];
    const float* b1  = (const float*)d_in[6];
    const float* w2  = (const float*)d_in[7];
    const float* b2  = (const float*)d_in[8];
    float* out = (float*)d_out;

    static int smem_set = 0;
    int smem_bytes = (12800 + 3456) * 4;   // 65024
    if (!smem_set) {
        cudaFuncSetAttribute(k_conv2, cudaFuncAttributeMaxDynamicSharedMemorySize, smem_bytes);
        smem_set = 1;
    }

    k_route<<<dim3(BATCH, 4), 256>>>(x, nw);
    k_mix<<<1, 512>>>(nb);
    k_conv1<<<dim3(NL * BATCH, 4, 2), 256>>>(x, cw1);
    k_conv2<<<dim3(NL * BATCH, 4), 256, smem_bytes>>>(cw2);
    k_mlp<<<NL * BATCH, 128>>>(w1, b1, w2, b2);
    k_final<<<BATCH, 128>>>(out);
}

// round 4
// speedup vs baseline: 4.2451x; 1.6986x over previous
#include <cuda_runtime.h>
#include <cuda_bf16.h>
#include <math.h>

#define BATCH 32
#define INC 3
#define OUTC 64
#define IMG 64
#define PH 32
#define NL 16
#define LEAFW 128
#define OUTW 100

typedef unsigned long long u64;

// Scratch
// h1 in bf16, channel-interleaved mma layout: [l*32+b][grp(4)][y32][x32][slot16]
__device__ __nv_bfloat16 g_h1[NL * BATCH * 4 * PH * PH * 16];
__device__ float g_feat[NL * BATCH * OUTC];
__device__ float g_scores[BATCH * 4];
__device__ float g_mix[BATCH * NL];
__device__ float g_logits[NL * BATCH * OUTW];

// ic (0..15) -> interleaved slot so mma k-quads {2c,2c+1,2c+8,2c+9} are 8B-contiguous
__device__ __forceinline__ int icslot(int ic) {
    return ((ic & 6) << 1) | ((ic >> 3) << 1) | (ic & 1);
}

__device__ __forceinline__ void mma_bf16(float* c, unsigned a0, unsigned a1,
                                         unsigned a2, unsigned a3,
                                         unsigned b0, unsigned b1) {
    asm("mma.sync.aligned.m16n8k16.row.col.f32.bf16.bf16.f32 "
        "{%0,%1,%2,%3}, {%4,%5,%6,%7}, {%8,%9}, {%0,%1,%2,%3};"
        : "+f"(c[0]), "+f"(c[1]), "+f"(c[2]), "+f"(c[3])
        : "r"(a0), "r"(a1), "r"(a2), "r"(a3), "r"(b0), "r"(b1));
}

// ---------------------------------------------------------------------------
// Routing
// ---------------------------------------------------------------------------
__global__ void k_route(const float* __restrict__ x, const float* __restrict__ nw) {
    int b = blockIdx.x, d = blockIdx.y, t = threadIdx.x;
    __shared__ float sw_[INC * 25];
    __shared__ float red[256];
    const float* w = nw + ((2 << d) - 2) * INC * 25;
    for (int i = t; i < INC * 25; i += 256) sw_[i] = w[i];
    __syncthreads();
    const float* xb = x + (long)b * INC * IMG * IMG;
    float m = -1e30f;
    for (int p = t; p < IMG * IMG; p += 256) {
        int y = p >> 6, xx = p & 63;
        float s = 0.f;
        #pragma unroll
        for (int c = 0; c < INC; c++)
            #pragma unroll
            for (int ky = 0; ky < 5; ky++) {
                int iy = y + ky - 2;
                if (iy < 0 || iy >= IMG) continue;
                #pragma unroll
                for (int kx = 0; kx < 5; kx++) {
                    int ix = xx + kx - 2;
                    if (ix < 0 || ix >= IMG) continue;
                    s += __ldg(&xb[(c << 12) + (iy << 6) + ix]) * sw_[c * 25 + ky * 5 + kx];
                }
            }
        m = fmaxf(m, s);
    }
    red[t] = m;
    __syncthreads();
    for (int s = 128; s > 0; s >>= 1) {
        if (t < s) red[t] = fmaxf(red[t], red[t + s]);
        __syncthreads();
    }
    if (t == 0) g_scores[b * 4 + d] = red[0];
}

// Mixture weights; also zeroes g_feat (conv2 accumulates via atomicMax)
__global__ void k_mix(const float* __restrict__ nb) {
    int t = threadIdx.x;
    for (int i = t; i < NL * BATCH * OUTC; i += 512) g_feat[i] = 0.f;
    if (t >= BATCH * NL) return;
    int b = t >> 4, l = t & 15;
    float m = 1.f;
    #pragma unroll
    for (int d = 0; d < 4; d++) {
        int j = l >> (4 - d);
        int bit = (l >> (3 - d)) & 1;
        float z = g_scores[b * 4 + d] + nb[(1 << d) - 1 + j];
        float be = 1.f / (1.f + expf(-z));
        m *= bit ? be : (1.f - be);
    }
    g_mix[b * NL + l] = m;
}

// ---------------------------------------------------------------------------
// conv1 (3->64, 5x5, SAME) + maxpool2 + relu -> g_h1 (bf16, interleaved layout)
// grid: (l*32+b, og 0..3, yt 0..1); block 256.
// thread: oc_l = t&15 (consecutive threads = consecutive channels for
// coalesced interleaved stores), lane16 = t>>4 selects pooled column half.
// ---------------------------------------------------------------------------
__global__ void __launch_bounds__(256) k_conv1(const float* __restrict__ x,
                                               const float* __restrict__ cw1) {
    __shared__ float sx[INC][36][68];
    __shared__ float sw_[16 * INC * 25];

    int lb = blockIdx.x;
    int b = lb & 31;
    int l = lb >> 5;
    int og = blockIdx.y;
    int yt = blockIdx.z;
    int t = threadIdx.x;

    for (int idx = t; idx < INC * 36 * 68; idx += 256) {
        int c = idx / (36 * 68);
        int rem = idx % (36 * 68);
        int yy = rem / 68, xx = rem % 68;
        int gy = yt * 32 + yy - 2, gx = xx - 2;
        float v = 0.f;
        if (gy >= 0 && gy < IMG && gx >= 0 && gx < IMG)
            v = x[(((long)b * INC + c) * IMG + gy) * IMG + gx];
        sx[c][yy][xx] = v;
    }
    for (int idx = t; idx < 16 * INC * 25; idx += 256) {
        sw_[idx] = cw1[(((long)l * OUTC + og * 16) * INC) * 25 + idx];
    }
    __syncthreads();

    int oc_l = t & 15;
    int lane16 = t >> 4;
    int slot = icslot(oc_l);
    __nv_bfloat16* hout = g_h1 + ((long)lb * 4 + og) * (PH * PH * 16);

    #pragma unroll 1
    for (int ps = 0; ps < 2; ps++) {
        int pc = lane16 + ps * 16;
        #pragma unroll 1
        for (int py = 0; py < 16; py++) {
            float a00 = 0.f, a01 = 0.f, a10 = 0.f, a11 = 0.f;
            #pragma unroll
            for (int c = 0; c < INC; c++) {
                float win[6][6];
                #pragma unroll
                for (int r = 0; r < 6; r++)
                    #pragma unroll
                    for (int q = 0; q < 6; q++)
                        win[r][q] = sx[c][2 * py + r][2 * pc + q];
                const float* wp = &sw_[(oc_l * INC + c) * 25];
                #pragma unroll
                for (int ky = 0; ky < 5; ky++)
                    #pragma unroll
                    for (int kx = 0; kx < 5; kx++) {
                        float wv = wp[ky * 5 + kx];
                        a00 = fmaf(win[ky][kx], wv, a00);
                        a01 = fmaf(win[ky][kx + 1], wv, a01);
                        a10 = fmaf(win[ky + 1][kx], wv, a10);
                        a11 = fmaf(win[ky + 1][kx + 1], wv, a11);
                    }
            }
            float v = fmaxf(fmaxf(a00, a01), fmaxf(a10, a11));
            v = fmaxf(v, 0.f);
            int prow = yt * 16 + py;
            hout[(prow * PH + pc) * 16 + slot] = __float2bfloat16(v);
        }
    }
}

// ---------------------------------------------------------------------------
// conv2 via bf16 mma m16n8k16, implicit GEMM.
// grid: (l*32+b, q 0..1); block 512 = 16 warps.
// block tile: 64 oc x 512 spatial (rows q*16..+15, 32 cols).
// warp: wm=wid&1 -> 32 oc (2 m16 tiles); wn=wid>>1 -> 2 rows x 32 cols
//       (8 n8-tiles). K loop: 4 chunks of 16 ic x 25 taps.
// smem: s_w [tap][oc64][slot16] bf16, row-padded to 2056B/tap (bank-safe STS);
//       s_in [20 rows][36 cols][slot16] bf16 (32B per position).
// Fragment loads: every A/B fragment = one LDS.64, warp-contiguous 256B.
// ---------------------------------------------------------------------------
__global__ void __launch_bounds__(512) k_conv2(const float* __restrict__ cw2) {
    extern __shared__ __align__(16) char dsm[];
    char* swb = dsm;              // 25 * 2056 = 51400 B
    char* sib = dsm + 51400;      // 20*36*32 = 23040 B

    int lb = blockIdx.x;
    int l = lb >> 5;
    int q = blockIdx.y;
    int t = threadIdx.x;
    int wid = t >> 5, lane = t & 31;
    int wm = wid & 1, wn = wid >> 1;
    int g = lane >> 2, c4 = lane & 3;

    float acc[2][8][4];
    #pragma unroll
    for (int i = 0; i < 2; i++)
        #pragma unroll
        for (int j = 0; j < 8; j++)
            #pragma unroll
            for (int k = 0; k < 4; k++) acc[i][j][k] = 0.f;

    const __nv_bfloat16* h1base = g_h1 + (long)lb * (4 * PH * PH * 16);
    const float* wbase = cw2 + (long)l * OUTC * OUTC * 25;

    #pragma unroll 1
    for (int cc = 0; cc < 4; cc++) {
        __syncthreads();
        // weights: global coalesced (tap fastest), padded-row STS
        for (int idx = t; idx < 25600; idx += 512) {
            int tap = idx % 25;
            int oi = idx / 25;
            int ic = oi & 15, oc = oi >> 4;
            float v = wbase[(oc * OUTC + cc * 16 + ic) * 25 + tap];
            *(__nv_bfloat16*)(swb + tap * 2056 + oc * 32 + icslot(ic) * 2) =
                __float2bfloat16(v);
        }
        // input slab 20x36 with halo: straight contiguous copy (u32 granules)
        const unsigned* hplane = (const unsigned*)(h1base + cc * (PH * PH * 16));
        for (int idx = t; idx < 5760; idx += 512) {
            int sl2 = idx & 7;
            int pos = idx >> 3;
            int xx = pos % 36, yy = pos / 36;
            int gy = q * 16 + yy - 2, gx = xx - 2;
            unsigned v = 0u;
            if (gy >= 0 && gy < PH && gx >= 0 && gx < PH)
                v = hplane[(gy * PH + gx) * 8 + sl2];
            *(unsigned*)(sib + pos * 32 + sl2 * 4) = v;
        }
        __syncthreads();

        #pragma unroll 1
        for (int ky = 0; ky < 5; ky++) {
            #pragma unroll 1
            for (int kx = 0; kx < 5; kx++) {
                int tap = ky * 5 + kx;
                const char* wtap = swb + tap * 2056 + 8 * c4;
                u64 aw0 = *(const u64*)(wtap + (wm * 32 + g) * 32);
                u64 aw1 = *(const u64*)(wtap + (wm * 32 + g + 8) * 32);
                u64 aw2 = *(const u64*)(wtap + (wm * 32 + 16 + g) * 32);
                u64 aw3 = *(const u64*)(wtap + (wm * 32 + 16 + g + 8) * 32);
                const char* bbase = sib + ((wn * 2 + ky) * 36 + g + kx) * 32 + 8 * c4;
                #pragma unroll
                for (int nt = 0; nt < 8; nt++) {
                    u64 bb = *(const u64*)(bbase + ((nt >> 2) * 36 + (nt & 3) * 8) * 32);
                    unsigned b0 = (unsigned)bb, b1 = (unsigned)(bb >> 32);
                    mma_bf16(acc[0][nt], (unsigned)aw0, (unsigned)aw1,
                             (unsigned)(aw0 >> 32), (unsigned)(aw1 >> 32), b0, b1);
                    mma_bf16(acc[1][nt], (unsigned)aw2, (unsigned)aw3,
                             (unsigned)(aw2 >> 32), (unsigned)(aw3 >> 32), b0, b1);
                }
            }
        }
    }

    // relu + spatial max -> atomicMax (g_feat zeroed in k_mix; values >= 0)
    #pragma unroll
    for (int mt = 0; mt < 2; mt++) {
        float mlo = 0.f, mhi = 0.f;  // relu floor
        #pragma unroll
        for (int nt = 0; nt < 8; nt++) {
            mlo = fmaxf(mlo, fmaxf(acc[mt][nt][0], acc[mt][nt][1]));
            mhi = fmaxf(mhi, fmaxf(acc[mt][nt][2], acc[mt][nt][3]));
        }
        mlo = fmaxf(mlo, __shfl_xor_sync(0xffffffffu, mlo, 1));
        mlo = fmaxf(mlo, __shfl_xor_sync(0xffffffffu, mlo, 2));
        mhi = fmaxf(mhi, __shfl_xor_sync(0xffffffffu, mhi, 1));
        mhi = fmaxf(mhi, __shfl_xor_sync(0xffffffffu, mhi, 2));
        if (c4 == 0) {
            int base = lb * OUTC + wm * 32 + mt * 16 + g;
            atomicMax((int*)&g_feat[base], __float_as_int(mlo));
            atomicMax((int*)&g_feat[base + 8], __float_as_int(mhi));
        }
    }
}

// ---------------------------------------------------------------------------
// Per-leaf MLP
// ---------------------------------------------------------------------------
__global__ void k_mlp(const float* __restrict__ w1, const float* __restrict__ b1,
                      const float* __restrict__ w2, const float* __restrict__ b2) {
    int lb = blockIdx.x;
    int l = lb >> 5, b = lb & 31;
    int t = threadIdx.x;
    __shared__ float sfeat[OUTC];
    __shared__ float shid[LEAFW];
    if (t < OUTC) sfeat[t] = g_feat[((long)l * BATCH + b) * OUTC + t];
    __syncthreads();
    float hsum = b1[l * LEAFW + t];
    #pragma unroll 8
    for (int k = 0; k < OUTC; k++)
        hsum = fmaf(sfeat[k], w1[((long)l * OUTC + k) * LEAFW + t], hsum);
    shid[t] = hsum;
    __syncthreads();
    if (t < OUTW) {
        float o = b2[l * OUTW + t];
        #pragma unroll 8
        for (int j = 0; j < LEAFW; j++)
            o = fmaf(shid[j], w2[((long)l * LEAFW + j) * OUTW + t], o);
        g_logits[((long)l * BATCH + b) * OUTW + t] = o;
    }
}

__global__ void k_final(float* __restrict__ out) {
    int b = blockIdx.x;
    int t = threadIdx.x;
    if (t < OUTW) {
        float s = 0.f;
        #pragma unroll
        for (int l = 0; l < NL; l++)
            s = fmaf(g_logits[((long)l * BATCH + b) * OUTW + t], g_mix[b * NL + l], s);
        out[b * OUTW + t] = s;
    }
}

// ---------------------------------------------------------------------------
extern "C" void kernel_launch(void* const* d_in, const int* in_sizes, int n_in,
                              void* d_out, int out_size) {
    const float* x   = (const float*)d_in[0];
    const float* nw  = (const float*)d_in[1];
    const float* nb  = (const float*)d_in[2];
    const float* cw1 = (const float*)d_in[3];
    const float* cw2 = (const float*)d_in[4];
    const float* w1  = (const float*)d_in[5];
    const float* b1  = (const float*)d_in[6];
    const float* w2  = (const float*)d_in[7];
    const float* b2  = (const float*)d_in[8];
    float* out = (float*)d_out;

    static int smem_set = 0;
    int smem_bytes = 51400 + 23040;  // 74440
    if (!smem_set) {
        cudaFuncSetAttribute(k_conv2, cudaFuncAttributeMaxDynamicSharedMemorySize,
                             smem_bytes);
        smem_set = 1;
    }

    k_route<<<dim3(BATCH, 4), 256>>>(x, nw);
    k_mix<<<1, 512>>>(nb);
    k_conv1<<<dim3(NL * BATCH, 4, 2), 256>>>(x, cw1);
    k_conv2<<<dim3(NL * BATCH, 2), 512, smem_bytes>>>(cw2);
    k_mlp<<<NL * BATCH, 128>>>(w1, b1, w2, b2);
    k_final<<<BATCH, 128>>>(out);
}

// round 5
// speedup vs baseline: 7.9582x; 1.8747x over previous
#include <cuda_runtime.h>
#include <cuda_bf16.h>
#include <math.h>

#define BATCH 32
#define INC 3
#define OUTC 64
#define IMG 64
#define PH 32
#define NL 16
#define LEAFW 128
#define OUTW 100

typedef unsigned long long u64;

// ---------------- scratch (no allocations allowed) ----------------
// h1 bf16, mma-interleaved: [lb][grp4][y32*x32][slot16]
__device__ __nv_bfloat16 g_h1[NL * BATCH * 4 * PH * PH * 16];
// conv2 weights pre-laid-out: [l][cc4][tap25][oc64][slot16]
__device__ __nv_bfloat16 g_w2b[NL * 4 * 25 * OUTC * 16];
// conv1 weights pre-laid-out: [l][kx5][oc64][slot16]  (slot k=(c,ky), 15 valid)
__device__ __nv_bfloat16 g_w1b[NL * 5 * OUTC * 16];
// im2col'd input for conv1: [b][y64][x64][slot16]  (slot k=(c,ky), row shift baked)
__device__ __nv_bfloat16 g_xcol[BATCH * IMG * IMG * 16];
__device__ float g_feat[NL * BATCH * OUTC];
__device__ float g_scores[BATCH * 4];
__device__ float g_mix[BATCH * NL];
__device__ float g_logits[NL * BATCH * OUTW];

// ic -> interleaved slot: k-quads {2c,2c+1,2c+8,2c+9} land 8B-contiguous
__device__ __forceinline__ int icslot(int ic) {
    return ((ic & 6) << 1) | ((ic >> 3) << 1) | (ic & 1);
}
// inverse of icslot
__device__ __forceinline__ int islot(int s) {
    return ((s >> 2) << 1) | ((s & 2) << 2) | (s & 1);
}

__device__ __forceinline__ void mma_bf16(float* c, unsigned a0, unsigned a1,
                                         unsigned a2, unsigned a3,
                                         unsigned b0, unsigned b1) {
    asm("mma.sync.aligned.m16n8k16.row.col.f32.bf16.bf16.f32 "
        "{%0,%1,%2,%3}, {%4,%5,%6,%7}, {%8,%9}, {%0,%1,%2,%3};"
        : "+f"(c[0]), "+f"(c[1]), "+f"(c[2]), "+f"(c[3])
        : "r"(a0), "r"(a1), "r"(a2), "r"(a3), "r"(b0), "r"(b1));
}

__device__ __forceinline__ void cp16(void* dst, const void* src, bool valid) {
    unsigned d = (unsigned)__cvta_generic_to_shared(dst);
    int sz = valid ? 16 : 0;
    asm volatile("cp.async.cg.shared.global [%0], [%1], 16, %2;"
                 :: "r"(d), "l"(__cvta_generic_to_global(src)), "r"(sz) : "memory");
}
__device__ __forceinline__ void cp_commit() {
    asm volatile("cp.async.commit_group;" ::: "memory");
}
__device__ __forceinline__ void cp_wait0() {
    asm volatile("cp.async.wait_group 0;" ::: "memory");
}

// ---------------------------------------------------------------------------
// Prep: weight re-layout + bf16 conversion (w2b blocks 0..6399, w1b 6400..6719)
// ---------------------------------------------------------------------------
__global__ void k_prep_w(const float* __restrict__ cw1, const float* __restrict__ cw2) {
    int bid = blockIdx.x;
    int t = threadIdx.x;
    if (bid < 6400) {
        int e = bid * 256 + t;                 // < 1,638,400
        int s = e & 15;
        int oc = (e >> 4) & 63;
        int r1 = e >> 10;
        int tap = r1 % 25;
        int r2 = r1 / 25;
        int cc = r2 & 3, l = r2 >> 2;
        int ic = islot(s);
        float v = cw2[(((long)l * OUTC + oc) * OUTC + cc * 16 + ic) * 25 + tap];
        g_w2b[e] = __float2bfloat16(v);
    } else {
        int e = (bid - 6400) * 256 + t;        // < 81,920
        int s = e & 15;
        int oc = (e >> 4) & 63;
        int r = e >> 10;
        int kx = r % 5, l = r / 5;
        int k = islot(s);
        float v = 0.f;
        if (k < 15) {
            int c = k / 5, ky = k % 5;
            v = cw1[(((long)l * OUTC + oc) * INC + c) * 25 + ky * 5 + kx];
        }
        g_w1b[e] = __float2bfloat16(v);
    }
}

// ---------------------------------------------------------------------------
// Prep: xcol[b][y][x][slot(k=(c,ky))] = x[b][c][y+ky-2][x]  (bf16, zero pad)
// grid (32, 64), block 256
// ---------------------------------------------------------------------------
__global__ void k_prep_x(const float* __restrict__ x) {
    int b = blockIdx.x, y = blockIdx.y, t = threadIdx.x;
    for (int e = t; e < 1024; e += 256) {
        int xx = e >> 4, s = e & 15;
        int k = islot(s);
        float v = 0.f;
        if (k < 15) {
            int c = k / 5, ky = k % 5;
            int yy = y + ky - 2;
            if (yy >= 0 && yy < IMG)
                v = x[(((long)b * INC + c) * IMG + yy) * IMG + xx];
        }
        g_xcol[(((long)b * IMG + y) * IMG + xx) * 16 + s] = __float2bfloat16(v);
    }
}

// ---------------------------------------------------------------------------
// Routing: all 4 depths in one pass per batch. grid 32, block 256,
// dynamic smem: slab[3][68][68] + 4*75 weights + reduce
// ---------------------------------------------------------------------------
__global__ void k_route(const float* __restrict__ x, const float* __restrict__ nw) {
    extern __shared__ float rsm[];
    float* slab = rsm;                 // 3*68*68 = 13872
    float* swf = rsm + 13872;          // 4*75
    __shared__ float red[8][4];

    int b = blockIdx.x, t = threadIdx.x;
    for (int idx = t; idx < 3 * 68 * 68; idx += 256) {
        int c = idx / 4624;
        int rem = idx % 4624;
        int yy = rem / 68, xx = rem % 68;
        int gy = yy - 2, gx = xx - 2;
        float v = 0.f;
        if (gy >= 0 && gy < IMG && gx >= 0 && gx < IMG)
            v = x[(((long)b * INC + c) * IMG + gy) * IMG + gx];
        slab[idx] = v;
    }
    for (int idx = t; idx < 4 * 75; idx += 256) {
        int d = idx / 75, j = idx % 75;
        swf[idx] = nw[((2 << d) - 2) * 75 + j];
    }
    __syncthreads();

    float sc[4] = {-1e30f, -1e30f, -1e30f, -1e30f};
    for (int p = t; p < IMG * IMG; p += 256) {
        int y = p >> 6, xx = p & 63;
        float a0 = 0.f, a1 = 0.f, a2 = 0.f, a3 = 0.f;
        #pragma unroll
        for (int c = 0; c < INC; c++)
            #pragma unroll
            for (int ky = 0; ky < 5; ky++)
                #pragma unroll
                for (int kx = 0; kx < 5; kx++) {
                    float v = slab[c * 4624 + (y + ky) * 68 + xx + kx];
                    int w = c * 25 + ky * 5 + kx;
                    a0 = fmaf(v, swf[w], a0);
                    a1 = fmaf(v, swf[75 + w], a1);
                    a2 = fmaf(v, swf[150 + w], a2);
                    a3 = fmaf(v, swf[225 + w], a3);
                }
        sc[0] = fmaxf(sc[0], a0); sc[1] = fmaxf(sc[1], a1);
        sc[2] = fmaxf(sc[2], a2); sc[3] = fmaxf(sc[3], a3);
    }
    #pragma unroll
    for (int d = 0; d < 4; d++)
        #pragma unroll
        for (int off = 16; off > 0; off >>= 1)
            sc[d] = fmaxf(sc[d], __shfl_xor_sync(0xffffffffu, sc[d], off));
    if ((t & 31) == 0)
        #pragma unroll
        for (int d = 0; d < 4; d++) red[t >> 5][d] = sc[d];
    __syncthreads();
    if (t < 4) {
        float m = red[0][t];
        #pragma unroll
        for (int w = 1; w < 8; w++) m = fmaxf(m, red[w][t]);
        g_scores[b * 4 + t] = m;
    }
}

// Mixture weights; also zeroes g_feat (conv2 accumulates via atomicMax)
__global__ void k_mix(const float* __restrict__ nb) {
    int t = threadIdx.x;
    for (int i = t; i < NL * BATCH * OUTC; i += 512) g_feat[i] = 0.f;
    if (t >= BATCH * NL) return;
    int b = t >> 4, l = t & 15;
    float m = 1.f;
    #pragma unroll
    for (int d = 0; d < 4; d++) {
        int j = l >> (4 - d);
        int bit = (l >> (3 - d)) & 1;
        float z = g_scores[b * 4 + d] + nb[(1 << d) - 1 + j];
        float be = 1.f / (1.f + expf(-z));
        m *= bit ? be : (1.f - be);
    }
    g_mix[b * NL + l] = m;
}

// ---------------------------------------------------------------------------
// conv1 via bf16 mma (k = (c,ky) baked into xcol; runtime taps = kx only)
// grid (lb=512, q=0..7); block 512 = 16 warps.
// block: 64 oc x (8 pre-pool rows x 64 cols). warp: wm=wid&1 (32 oc),
// wn=wid>>1: rp=wn>>1 (row pair), ch=wn&1 (col half). Epilogue: 2x2 pool+relu.
// ---------------------------------------------------------------------------
__global__ void __launch_bounds__(512) k_conv1m() {
    __shared__ __nv_bfloat16 sxc[8 * 68 * 16];   // 17408 B
    __shared__ __nv_bfloat16 sw1[5 * 64 * 16];   // 10240 B

    int lb = blockIdx.x;
    int l = lb >> 5, b = lb & 31;
    int q = blockIdx.y;
    int t = threadIdx.x;
    int wid = t >> 5, lane = t & 31;
    int wm = wid & 1, wn = wid >> 1;
    int rp = wn >> 1, ch = wn & 1;
    int g = lane >> 2, c4 = lane & 3;

    // stage slab: rows y=q*8..q*8+7, cols -2..65 (zero halo), u128 x2 per pos
    const __nv_bfloat16* xb = g_xcol + (long)b * (IMG * IMG * 16);
    for (int idx = t; idx < 1088; idx += 512) {
        int j = idx & 1, pos = idx >> 1;
        int col = pos % 68, row = pos / 68;
        int gx = col - 2;
        uint4 v = make_uint4(0, 0, 0, 0);
        if (gx >= 0 && gx < IMG)
            v = *(const uint4*)(xb + ((q * 8 + row) * IMG + gx) * 16 + j * 8);
        *(uint4*)(sxc + pos * 16 + j * 8) = v;
    }
    // stage weights (pure copy)
    const __nv_bfloat16* wsrc = g_w1b + (long)l * 5120;
    for (int idx = t; idx < 640; idx += 512)
        *(uint4*)(sw1 + idx * 8) = *(const uint4*)(wsrc + idx * 8);
    __syncthreads();

    float acc[2][8][4];
    #pragma unroll
    for (int i = 0; i < 2; i++)
        #pragma unroll
        for (int j = 0; j < 8; j++)
            #pragma unroll
            for (int k = 0; k < 4; k++) acc[i][j][k] = 0.f;

    #pragma unroll
    for (int kx = 0; kx < 5; kx++) {
        const char* wtap = (const char*)sw1 + kx * 2048 + 8 * c4;
        u64 aw0 = *(const u64*)(wtap + (wm * 32 + g) * 32);
        u64 aw1 = *(const u64*)(wtap + (wm * 32 + g + 8) * 32);
        u64 aw2 = *(const u64*)(wtap + (wm * 32 + 16 + g) * 32);
        u64 aw3 = *(const u64*)(wtap + (wm * 32 + 16 + g + 8) * 32);
        #pragma unroll
        for (int nt = 0; nt < 8; nt++) {
            int r = nt >> 2, xg = nt & 3;
            int col = ch * 32 + xg * 8 + g + kx;   // slab col (halo baked)
            int row = rp * 2 + r;
            u64 bb = *(const u64*)((const char*)sxc + (row * 68 + col) * 32 + 8 * c4);
            unsigned b0 = (unsigned)bb, b1 = (unsigned)(bb >> 32);
            mma_bf16(acc[0][nt], (unsigned)aw0, (unsigned)aw1,
                     (unsigned)(aw0 >> 32), (unsigned)(aw1 >> 32), b0, b1);
            mma_bf16(acc[1][nt], (unsigned)aw2, (unsigned)aw3,
                     (unsigned)(aw2 >> 32), (unsigned)(aw3 >> 32), b0, b1);
        }
    }

    // 2x2 pool + relu + store bf16 interleaved
    // thread holds cols {2c4, 2c4+1} of rows (oc) g and g+8, for 2 mt, 4 xg, 2 r
    int prow = q * 4 + rp;
    __nv_bfloat16* hout = g_h1 + (long)lb * (4 * PH * PH * 16);
    #pragma unroll
    for (int mt = 0; mt < 2; mt++) {
        int grp = wm * 2 + mt;
        #pragma unroll
        for (int xg = 0; xg < 4; xg++) {
            float* c0 = acc[mt][xg];        // r=0
            float* c1 = acc[mt][4 + xg];    // r=1
            float plo = fmaxf(fmaxf(c0[0], c0[1]), fmaxf(c1[0], c1[1]));
            float phi = fmaxf(fmaxf(c0[2], c0[3]), fmaxf(c1[2], c1[3]));
            plo = fmaxf(plo, 0.f);
            phi = fmaxf(phi, 0.f);
            int pcol = ch * 16 + xg * 4 + c4;
            long base = ((long)grp * (PH * PH) + prow * PH + pcol) * 16;
            hout[base + icslot(g)] = __float2bfloat16(plo);
            hout[base + icslot(g + 8)] = __float2bfloat16(phi);
        }
    }
}

// ---------------------------------------------------------------------------
// conv2 via bf16 mma, double-buffered cp.async staging from pre-laid-out w2b/h1
// grid (lb=512, q 0..1); block 512 = 16 warps.
// smem: 2 x (weights 51200 + input 23040) = 148480 B
// ---------------------------------------------------------------------------
__global__ void __launch_bounds__(512) k_conv2() {
    extern __shared__ __align__(16) char dsm[];
    char* wb[2] = {dsm, dsm + 51200};
    char* ib[2] = {dsm + 102400, dsm + 102400 + 23040};

    int lb = blockIdx.x;
    int l = lb >> 5;
    int q = blockIdx.y;
    int t = threadIdx.x;
    int wid = t >> 5, lane = t & 31;
    int wm = wid & 1, wn = wid >> 1;
    int g = lane >> 2, c4 = lane & 3;

    const __nv_bfloat16* h1base = g_h1 + (long)lb * (4 * PH * PH * 16);
    const __nv_bfloat16* w2base = g_w2b + (long)l * (4 * 25 * OUTC * 16);

    // ---- staging lambda (cp.async, one commit group per chunk) ----
    auto stage = [&](int cc, int buf) {
        const char* wsrc = (const char*)(w2base + (long)cc * 25 * OUTC * 16);
        char* wdst = wb[buf];
        for (int idx = t; idx < 3200; idx += 512)
            cp16(wdst + idx * 16, wsrc + idx * 16, true);
        const __nv_bfloat16* hplane = h1base + (long)cc * (PH * PH * 16);
        char* idst = ib[buf];
        for (int idx = t; idx < 1440; idx += 512) {
            int j = idx & 1, pos = idx >> 1;
            int xx = pos % 36, yy = pos / 36;
            int gy = q * 16 + yy - 2, gx = xx - 2;
            bool val = (gy >= 0 && gy < PH && gx >= 0 && gx < PH);
            const char* src = (const char*)(hplane +
                               ((val ? (gy * PH + gx) : 0) * 16) ) + j * 16;
            cp16(idst + pos * 32 + j * 16, src, val);
        }
        cp_commit();
    };

    float acc[2][8][4];
    #pragma unroll
    for (int i = 0; i < 2; i++)
        #pragma unroll
        for (int j = 0; j < 8; j++)
            #pragma unroll
            for (int k = 0; k < 4; k++) acc[i][j][k] = 0.f;

    stage(0, 0);

    #pragma unroll 1
    for (int cc = 0; cc < 4; cc++) {
        cp_wait0();
        __syncthreads();
        if (cc < 3) stage(cc + 1, (cc + 1) & 1);

        const char* swb = wb[cc & 1];
        const char* sib = ib[cc & 1];

        #pragma unroll 1
        for (int ky = 0; ky < 5; ky++) {
            #pragma unroll 1
            for (int kx = 0; kx < 5; kx++) {
                int tap = ky * 5 + kx;
                const char* wtap = swb + tap * 2048 + 8 * c4;
                u64 aw0 = *(const u64*)(wtap + (wm * 32 + g) * 32);
                u64 aw1 = *(const u64*)(wtap + (wm * 32 + g + 8) * 32);
                u64 aw2 = *(const u64*)(wtap + (wm * 32 + 16 + g) * 32);
                u64 aw3 = *(const u64*)(wtap + (wm * 32 + 16 + g + 8) * 32);
                const char* bbase = sib + ((wn * 2 + ky) * 36 + g + kx) * 32 + 8 * c4;
                #pragma unroll
                for (int nt = 0; nt < 8; nt++) {
                    u64 bb = *(const u64*)(bbase + ((nt >> 2) * 36 + (nt & 3) * 8) * 32);
                    unsigned b0 = (unsigned)bb, b1 = (unsigned)(bb >> 32);
                    mma_bf16(acc[0][nt], (unsigned)aw0, (unsigned)aw1,
                             (unsigned)(aw0 >> 32), (unsigned)(aw1 >> 32), b0, b1);
                    mma_bf16(acc[1][nt], (unsigned)aw2, (unsigned)aw3,
                             (unsigned)(aw2 >> 32), (unsigned)(aw3 >> 32), b0, b1);
                }
            }
        }
        __syncthreads();
    }

    // relu + spatial max -> atomicMax (g_feat zeroed in k_mix; values >= 0)
    #pragma unroll
    for (int mt = 0; mt < 2; mt++) {
        float mlo = 0.f, mhi = 0.f;
        #pragma unroll
        for (int nt = 0; nt < 8; nt++) {
            mlo = fmaxf(mlo, fmaxf(acc[mt][nt][0], acc[mt][nt][1]));
            mhi = fmaxf(mhi, fmaxf(acc[mt][nt][2], acc[mt][nt][3]));
        }
        mlo = fmaxf(mlo, __shfl_xor_sync(0xffffffffu, mlo, 1));
        mlo = fmaxf(mlo, __shfl_xor_sync(0xffffffffu, mlo, 2));
        mhi = fmaxf(mhi, __shfl_xor_sync(0xffffffffu, mhi, 1));
        mhi = fmaxf(mhi, __shfl_xor_sync(0xffffffffu, mhi, 2));
        if (c4 == 0) {
            int base = lb * OUTC + wm * 32 + mt * 16 + g;
            atomicMax((int*)&g_feat[base], __float_as_int(mlo));
            atomicMax((int*)&g_feat[base + 8], __float_as_int(mhi));
        }
    }
}

// ---------------------------------------------------------------------------
// Per-leaf MLP
// ---------------------------------------------------------------------------
__global__ void k_mlp(const float* __restrict__ w1, const float* __restrict__ b1,
                      const float* __restrict__ w2, const float* __restrict__ b2) {
    int lb = blockIdx.x;
    int l = lb >> 5, b = lb & 31;
    int t = threadIdx.x;
    __shared__ float sfeat[OUTC];
    __shared__ float shid[LEAFW];
    if (t < OUTC) sfeat[t] = g_feat[((long)l * BATCH + b) * OUTC + t];
    __syncthreads();
    float hsum = b1[l * LEAFW + t];
    #pragma unroll 8
    for (int k = 0; k < OUTC; k++)
        hsum = fmaf(sfeat[k], w1[((long)l * OUTC + k) * LEAFW + t], hsum);
    shid[t] = hsum;
    __syncthreads();
    if (t < OUTW) {
        float o = b2[l * OUTW + t];
        #pragma unroll 8
        for (int j = 0; j < LEAFW; j++)
            o = fmaf(shid[j], w2[((long)l * LEAFW + j) * OUTW + t], o);
        g_logits[((long)l * BATCH + b) * OUTW + t] = o;
    }
}

__global__ void k_final(float* __restrict__ out) {
    int b = blockIdx.x;
    int t = threadIdx.x;
    if (t < OUTW) {
        float s = 0.f;
        #pragma unroll
        for (int l = 0; l < NL; l++)
            s = fmaf(g_logits[((long)l * BATCH + b) * OUTW + t], g_mix[b * NL + l], s);
        out[b * OUTW + t] = s;
    }
}

// ---------------------------------------------------------------------------
extern "C" void kernel_launch(void* const* d_in, const int* in_sizes, int n_in,
                              void* d_out, int out_size) {
    const float* x   = (const float*)d_in[0];
    const float* nw  = (const float*)d_in[1];
    const float* nb  = (const float*)d_in[2];
    const float* cw1 = (const float*)d_in[3];
    const float* cw2 = (const float*)d_in[4];
    const float* w1  = (const float*)d_in[5];
    const float* b1  = (const float*)d_in[6];
    const float* w2  = (const float*)d_in[7];
    const float* b2  = (const float*)d_in[8];
    float* out = (float*)d_out;

    cudaFuncSetAttribute(k_conv2, cudaFuncAttributeMaxDynamicSharedMemorySize, 148480);
    cudaFuncSetAttribute(k_route, cudaFuncAttributeMaxDynamicSharedMemorySize, 56688);

    k_prep_w<<<6720, 256>>>(cw1, cw2);
    k_prep_x<<<dim3(32, 64), 256>>>(x);
    k_route<<<32, 256, (13872 + 300) * 4>>>(x, nw);
    k_mix<<<1, 512>>>(nb);
    k_conv1m<<<dim3(NL * BATCH, 8), 512>>>();
    k_conv2<<<dim3(NL * BATCH, 2), 512, 148480>>>();
    k_mlp<<<NL * BATCH, 128>>>(w1, b1, w2, b2);
    k_final<<<BATCH, 128>>>(out);
}